// round 16
// baseline (speedup 1.0000x reference)
#include <cuda_runtime.h>
#include <math.h>
#include <stdint.h>

// ContrastLoss: B=4, C=4096, K=1.  (Converged kernel.)
//
// lse_pairs_b   = log(sum_{lab=0} e^{pred}) + log(sum_{lab=1} e^{-pred})
// loss_contrast = (1/B) * sum_b logaddexp(lse_pairs_b, 0)
// loss_aux      = (1/B) * sum_b mean_c (aux - aux_label)^2
//
// Structure (best of 10 measured variants): 8-CTA cluster x 512 threads,
// 4 elems/thread, octet-depth warp reduce (3 butterfly steps), octet-leader
// DSMEM v4 stores into rank 0 (512 slots), one cluster barrier, fully
// parallel finalize in rank 0 warp 0. DSMEM addressing is hoisted above the
// load-dependent math so it overlaps the memory round trip.
// Deterministic: fixed slots, fixed butterfly order.

#define FULL 0xFFFFFFFFu
#define NBLK 8
#define NTHR 512
#define WPB  (NTHR / 32)              // 16 warps per CTA
#define NSLOT (NBLK * WPB * 4)        // 512 slots (4 octets per warp)

__device__ __forceinline__ uint32_t smem_u32(const void* p) {
    uint32_t a;
    asm("{ .reg .u64 t; cvta.to.shared.u64 t, %1; cvt.u32.u64 %0, t; }"
        : "=r"(a) : "l"(p));
    return a;
}

__device__ __forceinline__ void acc_elem(float v, int lab, float& sn, float& sp) {
    // exp(+v) if lab==0 else exp(-v): flip the sign bit when lab==1.
    float t = __int_as_float(__float_as_int(v) ^ (lab << 31));
    float e = __expf(t);
    sn += (lab == 0) ? e : 0.f;
    sp += (lab == 0) ? 0.f : e;
}

__global__ __launch_bounds__(NTHR, 1) __cluster_dims__(NBLK, 1, 1)
void contrast_loss_kernel(const float* __restrict__ contrast,
                          const int*   __restrict__ label,
                          const float* __restrict__ aux,
                          const float* __restrict__ aux_label,
                          float* __restrict__ out) {
    // Identical layout in every CTA; only rank 0's copy is used (mapa
    // translates local slot addresses to rank 0's shared memory).
    __shared__ float4 sclus[NSLOT];

    int tid = threadIdx.x;
    uint32_t rank;
    asm("mov.u32 %0, %%cluster_ctarank;" : "=r"(rank));

    // Each CTA covers 2048 contiguous elements = half of one batch.
    int base = (int)rank * 2048 + tid * 4;

    // Issue all 4 vector loads first (MLP = 4); everything below the loads
    // that doesn't depend on them overlaps the memory round trip.
    float4 c  = *reinterpret_cast<const float4*>(contrast + base);
    int4   l  = *reinterpret_cast<const int4*>(label + base);
    float4 a  = *reinterpret_cast<const float4*>(aux + base);
    float4 al = *reinterpret_cast<const float4*>(aux_label + base);

    // Hoisted DSMEM addressing: slot index + mapa overlap the loads.
    int slot = (int)rank * (WPB * 4) + ((tid >> 5) << 2) + ((tid >> 3) & 3);
    uint32_t local = smem_u32(&sclus[slot]);
    uint32_t rem;
    asm volatile("mapa.shared::cluster.u32 %0, %1, 0;" : "=r"(rem) : "r"(local));

    float sn = 0.f, sp = 0.f, ax = 0.f;

    acc_elem(c.x, l.x, sn, sp);
    acc_elem(c.y, l.y, sn, sp);
    acc_elem(c.z, l.z, sn, sp);
    acc_elem(c.w, l.w, sn, sp);

    float d;
    d = a.x - al.x; ax = fmaf(d, d, ax);
    d = a.y - al.y; ax = fmaf(d, d, ax);
    d = a.z - al.z; ax = fmaf(d, d, ax);
    d = a.w - al.w; ax = fmaf(d, d, ax);

    // Octet-depth reduce: 3 butterfly steps; every 8-lane octet holds its sum.
    #pragma unroll
    for (int o = 1; o < 8; o <<= 1) {
        sn += __shfl_xor_sync(FULL, sn, o);
        sp += __shfl_xor_sync(FULL, sp, o);
        ax += __shfl_xor_sync(FULL, ax, o);
    }

    // 4 octet-leader lanes per warp store partials into rank 0's smem.
    if ((tid & 7) == 0) {
        asm volatile("st.shared::cluster.v4.f32 [%0], {%1, %2, %3, %4};"
                     :: "r"(rem), "f"(sn), "f"(sp), "f"(ax), "f"(0.f) : "memory");
    }

    // One cluster barrier: arrive (release) orders the DSMEM stores;
    // wait (acquire) makes them visible to rank 0's readers.
    asm volatile("barrier.cluster.arrive.aligned;" ::: "memory");
    asm volatile("barrier.cluster.wait.aligned;"   ::: "memory");

    if (rank == 0 && tid < 32) {
        // 512 slots; CTA r owns [64r, 64r+64) -> batch b owns [128b, 128b+128).
        // Lane l: batch = l>>3, idx = l&7; reads 16 slots 128b + idx + 8k.
        int b   = tid >> 3;
        int idx = tid & 7;
        const float4* sb = &sclus[128 * b + idx];
        float bn = 0.f, bp = 0.f, ba = 0.f;
        #pragma unroll
        for (int k = 0; k < 16; k++) {
            float4 p = sb[8 * k];
            bn += p.x; bp += p.y; ba += p.z;
        }

        // Octet butterfly: lanes within an octet share a batch.
        #pragma unroll
        for (int o = 1; o < 8; o <<= 1) {
            bn += __shfl_xor_sync(FULL, bn, o);
            bp += __shfl_xor_sync(FULL, bp, o);
            ba += __shfl_xor_sync(FULL, ba, o);
        }

        // Per-batch losses computed in parallel across the 4 octets.
        // Empty class -> bn or bp == 0 -> lse = -inf -> contras = 0.
        float lse     = __logf(bn) + __logf(bp);
        float contras = fmaxf(lse, 0.f) + log1pf(__expf(-fabsf(lse)));
        float laux    = ba * (1.0f / 4096.0f);

        // Keep only octet leaders, then butterfly across octets.
        if (idx != 0) { contras = 0.f; laux = 0.f; }
        contras += __shfl_xor_sync(FULL, contras, 8);
        laux    += __shfl_xor_sync(FULL, laux, 8);
        contras += __shfl_xor_sync(FULL, contras, 16);
        laux    += __shfl_xor_sync(FULL, laux, 16);

        if (tid == 0) {
            out[0] = contras * 0.25f;   // / n_items (B=4)
            out[1] = laux * 0.25f;
        }
    }
}

extern "C" void kernel_launch(void* const* d_in, const int* in_sizes, int n_in,
                              void* d_out, int out_size) {
    const float* contrast  = (const float*)d_in[0];
    const int*   label     = (const int*)d_in[1];
    const float* aux       = (const float*)d_in[2];
    const float* aux_label = (const float*)d_in[3];
    float* out = (float*)d_out;

    contrast_loss_kernel<<<NBLK, NTHR>>>(contrast, label, aux, aux_label, out);
}